// round 11
// baseline (speedup 1.0000x reference)
#include <cuda_runtime.h>
#include <cstdint>

// ---- f32x2 packed helpers (sm_103a). Packed lanes round identically to scalar.
__device__ __forceinline__ unsigned long long mul2(unsigned long long a, unsigned long long b) {
    unsigned long long r;
    asm("mul.rn.f32x2 %0, %1, %2;" : "=l"(r) : "l"(a), "l"(b));
    return r;
}
__device__ __forceinline__ unsigned long long add2(unsigned long long a, unsigned long long b) {
    unsigned long long r;
    asm("add.rn.f32x2 %0, %1, %2;" : "=l"(r) : "l"(a), "l"(b));
    return r;
}
__device__ __forceinline__ unsigned long long pk2(float lo, float hi) {
    unsigned long long r;
    asm("mov.b64 %0, {%1, %2};" : "=l"(r) : "f"(lo), "f"(hi));
    return r;
}
__device__ __forceinline__ float2 upk(unsigned long long v) {
    float2 r;
    asm("mov.b64 {%0, %1}, %2;" : "=f"(r.x), "=f"(r.y) : "l"(v));
    return r;
}

struct SMM { float S, mn; };

// u_j = xp_j * a_j (all non-negative: xp = |x| pairs, a = |grid| pairs).
// S = balanced sum, mn = min. Fixed op shapes -> deterministic rounding.
__device__ __forceinline__ SMM score8(unsigned long long xp0, unsigned long long xp1,
                                      unsigned long long xp2, unsigned long long xp3,
                                      unsigned long long a01, unsigned long long a23,
                                      unsigned long long a45, unsigned long long a67)
{
    unsigned long long u0 = mul2(xp0, a01);
    unsigned long long u1 = mul2(xp1, a23);
    unsigned long long u2 = mul2(xp2, a45);
    unsigned long long u3 = mul2(xp3, a67);
    unsigned long long r  = add2(add2(u0, u1), add2(u2, u3));
    float2 rr = upk(r);
    float2 f0 = upk(u0), f1 = upk(u1), f2 = upk(u2), f3 = upk(u3);
    SMM o;
    o.S  = rr.x + rr.y;
    o.mn = fminf(fminf(fminf(f0.x, f0.y), fminf(f1.x, f1.y)),
                 fminf(fminf(f2.x, f2.y), fminf(f3.x, f3.y)));
    return o;
}

// 512 blocks x 256 threads. Block bk: ipair = bk>>2, jg0 = 2*(bk&3); warp w:
// dm=w>>2, dn=w&3; rows row[tt] = (2*ipair+dm)*32 + 4*(jg0+tt)+dn (tt=0,1).
// Table: s_a[A][0..7] = |grid[A<<8]| (only comp 7 can be negative);
// s_norm[A] = norm with sign(a7) folded in (stride-1 -> conflict-free LDS).
__global__ void __launch_bounds__(256, 4) e8p_fused_kernel(
    const float* __restrict__ X,
    const float* __restrict__ grid,
    const float* __restrict__ grid_norm,
    float* __restrict__ out)
{
    __shared__ __align__(16) float s_a[256][12];   // stride 12 -> LDS.128 conflict-free
    __shared__ float s_norm[256];
    __shared__ int s_bestc[16];

    const int tid = threadIdx.x;
    {
        const int A = tid;                         // exactly 256 threads: one round
        const float4* g4 = reinterpret_cast<const float4*>(grid + ((size_t)A << 11));
        float4 a0 = g4[0], a1 = g4[1];
        const float na = grid_norm[A << 8];
        float4* d4 = reinterpret_cast<float4*>(s_a[A]);
        d4[0] = make_float4(fabsf(a0.x), fabsf(a0.y), fabsf(a0.z), fabsf(a0.w));
        d4[1] = make_float4(fabsf(a1.x), fabsf(a1.y), fabsf(a1.z), fabsf(a1.w));
        s_norm[A] = (a1.w < 0.f) ? -na : na;       // fold sign(a7) into norm
    }
    __syncthreads();

    const int warp = tid >> 5, lane = tid & 31;
    const int ipair = blockIdx.x >> 2;             // 0..127
    const int jg0   = (blockIdx.x & 3) * 2;        // 0,2,4,6
    const int dm = warp >> 2, dn = warp & 3;

    // Component j of the value vector <- bit SHUF[j] of the sign field.
    // SHUF = {0,4,1,5,2,6,3,7} -> BITS[j] = 1 << SHUF[j].
    constexpr unsigned BITS[8] = {1u<<0, 1u<<4, 1u<<1, 1u<<5, 1u<<2, 1u<<6, 1u<<3, 1u<<7};

    int   row[2];
    float p1c[2];
    unsigned long long xp[2][2][4];                // [tt][parity][j-pair] packed |x|
    unsigned maskx[2][2];                          // [tt][parity] sign masks (BITS domain)
    int px[2][2];                                  // parity of maskx, in bit 31
    #pragma unroll
    for (int tt = 0; tt < 2; tt++) {
        row[tt] = (2 * ipair + dm) * 32 + 4 * (jg0 + tt) + dn;
        const float4* xr4 = reinterpret_cast<const float4*>(X + (size_t)row[tt] * 8);
        float4 v0 = xr4[0], v1 = xr4[1];
        float x[8] = {v0.x, v0.y, v0.z, v0.w, v1.x, v1.y, v1.z, v1.w};
        float sx = 0.f;
        unsigned m0 = 0, m1 = 0;
        float x25[8];
        #pragma unroll
        for (int j = 0; j < 8; j++) {
            sx += x[j];
            x25[j] = x[j] + 0.25f;
            if (x[j]   < 0.f) m0 |= BITS[j];
            if (x25[j] < 0.f) m1 |= BITS[j];
        }
        #pragma unroll
        for (int jj = 0; jj < 4; jj++) {
            xp[tt][0][jj] = pk2(fabsf(x[2*jj]),   fabsf(x[2*jj+1]));
            xp[tt][1][jj] = pk2(fabsf(x25[2*jj]), fabsf(x25[2*jj+1]));
        }
        p1c[tt] = -0.5f * sx - 0.5f;
        maskx[tt][0] = m0;  px[tt][0] = (__popc(m0) & 1) << 31;
        maskx[tt][1] = m1;  px[tt][1] = (__popc(m1) & 1) << 31;
    }

    float best[2] = {-1e30f, -1e30f};
    int   bA[2]   = {0, 0};

    #pragma unroll
    for (int k = 0; k < 8; k++) {
        const int A = lane + (k << 5);
        const ulonglong2* pa = reinterpret_cast<const ulonglong2*>(s_a[A]);
        ulonglong2 q0 = pa[0], q1 = pa[1];         // (a0,a1),(a2,a3),(a4,a5),(a6,a7)
        const float nas  = s_norm[A];
        const int   ns   = __float_as_int(nas);    // sign bit = sign(a7)
        const float nabs = fabsf(nas);

        #pragma unroll
        for (int tt = 0; tt < 2; tt++) {
            SMM s0 = score8(xp[tt][0][0], xp[tt][0][1], xp[tt][0][2], xp[tt][0][3],
                            q0.x, q0.y, q1.x, q1.y);
            SMM s1 = score8(xp[tt][1][0], xp[tt][1][1], xp[tt][1][2], xp[tt][1][3],
                            q0.x, q0.y, q1.x, q1.y);
            // odd total parity (row-parity XOR sign(a7)) -> flip cheapest component
            float Sp0 = ((ns ^ px[tt][0]) < 0) ? fmaf(-2.f, s0.mn, s0.S) : s0.S;
            float Sp1 = ((ns ^ px[tt][1]) < 0) ? fmaf(-2.f, s1.mn, s1.S) : s1.S;
            float sc0 = fmaf(2.f, Sp0, -nabs);
            float sc1 = fmaf(2.f, Sp1, -nabs) + p1c[tt];
            float scm = fmaxf(sc0, sc1);           // parity re-decided at winner
            if (scm > best[tt]) { best[tt] = scm; bA[tt] = A; }   // first-wins: lowest A
        }
    }

    #pragma unroll
    for (int tt = 0; tt < 2; tt++) {
        // Warp argmax (butterfly; tie -> lowest A, matching argmax first-max).
        float b = best[tt]; int cA = bA[tt];
        #pragma unroll
        for (int off = 16; off; off >>= 1) {
            float ob = __shfl_xor_sync(0xffffffffu, b,  off);
            int   oc = __shfl_xor_sync(0xffffffffu, cA, off);
            if (ob > b || (ob == b && oc < cA)) { b = ob; cA = oc; }
        }

        // Winner recompute (all lanes, broadcast LDS) with the SAME packed ops.
        const ulonglong2* pa = reinterpret_cast<const ulonglong2*>(s_a[cA]);
        ulonglong2 q0 = pa[0], q1 = pa[1];
        const float nas  = s_norm[cA];
        const int   ns   = __float_as_int(nas);
        const float nabs = fabsf(nas);
        SMM s0 = score8(xp[tt][0][0], xp[tt][0][1], xp[tt][0][2], xp[tt][0][3],
                        q0.x, q0.y, q1.x, q1.y);
        SMM s1 = score8(xp[tt][1][0], xp[tt][1][1], xp[tt][1][2], xp[tt][1][3],
                        q0.x, q0.y, q1.x, q1.y);
        float Sp0 = ((ns ^ px[tt][0]) < 0) ? fmaf(-2.f, s0.mn, s0.S) : s0.S;
        float Sp1 = ((ns ^ px[tt][1]) < 0) ? fmaf(-2.f, s1.mn, s1.S) : s1.S;
        float sc0 = fmaf(2.f, Sp0, -nabs);
        float sc1 = fmaf(2.f, Sp1, -nabs) + p1c[tt];
        const int pw = (sc1 > sc0) ? 1 : 0;        // p0 wins exact ties

        // Scalar magnitudes of the winning parity for the first-min scan.
        unsigned long long y0 = pw ? xp[tt][1][0] : xp[tt][0][0];
        unsigned long long y1 = pw ? xp[tt][1][1] : xp[tt][0][1];
        unsigned long long y2 = pw ? xp[tt][1][2] : xp[tt][0][2];
        unsigned long long y3 = pw ? xp[tt][1][3] : xp[tt][0][3];
        float2 g0 = upk(mul2(y0, q0.x)), g1 = upk(mul2(y1, q0.y));
        float2 g2 = upk(mul2(y2, q1.x)), g3 = upk(mul2(y3, q1.y));
        float u[8] = {g0.x, g0.y, g1.x, g1.y, g2.x, g2.y, g3.x, g3.y};

        unsigned m = maskx[tt][pw] ^ ((ns < 0) ? 0x80u : 0u);
        float mnv = 1e30f; unsigned mnbit = 0;
        #pragma unroll
        for (int j = 0; j < 8; j++) {
            if (u[j] < mnv) { mnv = u[j]; mnbit = BITS[j]; }  // strict: first min
        }
        if (__popc(m) & 1) m ^= mnbit;
        const int bestc = (cA << 8) | ((int)m ^ pw);          // p=1 flips bit 0

        if (lane < 8) {
            out[(size_t)row[tt] * 8 + lane] = grid[(size_t)bestc * 8 + lane];  // vals
        }
        if (lane == 0) {
            out[65536 + row[tt]] = (float)bestc;              // idxs
            s_bestc[tt * 8 + warp] = bestc;                   // slot = tt*8 + (dm*4+dn)
        }
    }
    __syncthreads();

    // ---- Block-local _pack_idxs (int32 / x64-disabled semantics: the reference's
    //      sign32 << 32 saturates to 0 in XLA; packed = int32 wrap of abs32).
    if (tid < 4) {
        const int ttp = tid >> 1, jj = tid & 1;
        const int base = ttp * 8;
        const int j = 2 * jg0 + tid;                          // column-pair index 0..15
        int q00 = s_bestc[base +     2 * jj    ];             // (2i,   2j)
        int q10 = s_bestc[base + 4 + 2 * jj    ];             // (2i+1, 2j)
        int q01 = s_bestc[base +     2 * jj + 1];             // (2i,   2j+1)
        int q11 = s_bestc[base + 4 + 2 * jj + 1];             // (2i+1, 2j+1)

        unsigned abs32 = (unsigned)(q00 >> 8)
                       | ((unsigned)(q10 >> 8) << 8)
                       | ((unsigned)(q01 >> 8) << 16)
                       | ((unsigned)(q11 >> 8) << 24);

        // L from (i, j): L = (i>>3)<<7 | (j>>2)<<5 | (i&7)<<2 | (j&3)
        const int i = ipair;
        const int L = ((i >> 3) << 7) | ((j >> 2) << 5) | ((i & 7) << 2) | (j & 3);
        out[73728 + L] = (float)(int)abs32;                   // int32 wrap, f32 cast
    }
}

extern "C" void kernel_launch(void* const* d_in, const int* in_sizes, int n_in,
                              void* d_out, int out_size)
{
    const float* X         = (const float*)d_in[0];   // 256*32*8 = 65536
    const float* grid      = (const float*)d_in[1];   // 65536*8
    const float* grid_norm = (const float*)d_in[2];   // 65536
    float* out = (float*)d_out;                       // [vals | idxs | packed] fp32

    e8p_fused_kernel<<<512, 256>>>(X, grid, grid_norm, out);
}

// round 13
// speedup vs baseline: 1.0498x; 1.0498x over previous
#include <cuda_runtime.h>
#include <cstdint>

// ---- f32x2 packed helpers (sm_103a). Packed lanes round identically to scalar.
__device__ __forceinline__ unsigned long long mul2(unsigned long long a, unsigned long long b) {
    unsigned long long r;
    asm("mul.rn.f32x2 %0, %1, %2;" : "=l"(r) : "l"(a), "l"(b));
    return r;
}
__device__ __forceinline__ unsigned long long add2(unsigned long long a, unsigned long long b) {
    unsigned long long r;
    asm("add.rn.f32x2 %0, %1, %2;" : "=l"(r) : "l"(a), "l"(b));
    return r;
}
__device__ __forceinline__ unsigned long long pk2(float lo, float hi) {
    unsigned long long r;
    asm("mov.b64 %0, {%1, %2};" : "=l"(r) : "f"(lo), "f"(hi));
    return r;
}
__device__ __forceinline__ float2 upk(unsigned long long v) {
    float2 r;
    asm("mov.b64 {%0, %1}, %2;" : "=f"(r.x), "=f"(r.y) : "l"(v));
    return r;
}

struct SMM { float S, mn; };

// u_j = xp_j * a_j (all non-negative: xp = |x| pairs, a = |grid| pairs).
// S = balanced sum, mn = min. Fixed op shapes -> deterministic rounding.
__device__ __forceinline__ SMM score8(unsigned long long xp0, unsigned long long xp1,
                                      unsigned long long xp2, unsigned long long xp3,
                                      unsigned long long a01, unsigned long long a23,
                                      unsigned long long a45, unsigned long long a67)
{
    unsigned long long u0 = mul2(xp0, a01);
    unsigned long long u1 = mul2(xp1, a23);
    unsigned long long u2 = mul2(xp2, a45);
    unsigned long long u3 = mul2(xp3, a67);
    unsigned long long r  = add2(add2(u0, u1), add2(u2, u3));
    float2 rr = upk(r);
    float2 f0 = upk(u0), f1 = upk(u1), f2 = upk(u2), f3 = upk(u3);
    SMM o;
    o.S  = rr.x + rr.y;
    o.mn = fminf(fminf(fminf(f0.x, f0.y), fminf(f1.x, f1.y)),
                 fminf(fminf(f2.x, f2.y), fminf(f3.x, f3.y)));
    return o;
}

// 256 blocks x 512 threads. Block bk: ipair = bk>>1 (row-pair of the 256x32
// idx matrix), half = bk&1 (16-column half). Warp w (0..15): dm = w&1,
// c = w>>1; entries (tt=0,1): m = 2*ipair+dm, n = 16*half + 2*c + tt.
// All 4 idx entries of each packed word live inside one block -> local pack.
// Table: s_a[A][0..7] = |grid[A<<8]| (only comp 7 can be negative);
// s_norm[A] = norm with sign(a7) folded in (stride-1 -> conflict-free LDS).
// NOTE: sign(a7) is NOT contiguous in A (verified R12 failure) -> general
// per-candidate select everywhere.
__global__ void __launch_bounds__(512, 2) e8p_fused_kernel(
    const float* __restrict__ X,
    const float* __restrict__ grid,
    const float* __restrict__ grid_norm,
    float* __restrict__ out)
{
    __shared__ __align__(16) float s_a[256][12];   // stride 12 -> LDS.128 conflict-free
    __shared__ float s_norm[256];
    __shared__ int s_bestc[32];

    const int tid = threadIdx.x;
    if (tid < 256) {
        const int A = tid;
        const float4* g4 = reinterpret_cast<const float4*>(grid + ((size_t)A << 11));
        float4 a0 = g4[0], a1 = g4[1];
        const float na = grid_norm[A << 8];
        float4* d4 = reinterpret_cast<float4*>(s_a[A]);
        d4[0] = make_float4(fabsf(a0.x), fabsf(a0.y), fabsf(a0.z), fabsf(a0.w));
        d4[1] = make_float4(fabsf(a1.x), fabsf(a1.y), fabsf(a1.z), fabsf(a1.w));
        s_norm[A] = (a1.w < 0.f) ? -na : na;       // fold sign(a7) into norm
    }
    __syncthreads();

    const int warp = tid >> 5, lane = tid & 31;
    const int ipair = blockIdx.x >> 1;             // 0..127
    const int half  = blockIdx.x & 1;              // 0..1
    const int dm = warp & 1, c = warp >> 1;        // c = 0..7

    // Component j of the value vector <- bit SHUF[j] of the sign field.
    // SHUF = {0,4,1,5,2,6,3,7} -> BITS[j] = 1 << SHUF[j].
    constexpr unsigned BITS[8] = {1u<<0, 1u<<4, 1u<<1, 1u<<5, 1u<<2, 1u<<6, 1u<<3, 1u<<7};

    int   row[2];
    float p1c[2];
    unsigned long long xp[2][2][4];                // [tt][parity][j-pair] packed |x|
    unsigned maskx[2][2];                          // [tt][parity] sign masks (BITS domain)
    int px[2][2];                                  // parity of maskx, in bit 31
    #pragma unroll
    for (int tt = 0; tt < 2; tt++) {
        row[tt] = (2 * ipair + dm) * 32 + 16 * half + 2 * c + tt;
        const float4* xr4 = reinterpret_cast<const float4*>(X + (size_t)row[tt] * 8);
        float4 v0 = xr4[0], v1 = xr4[1];
        float x[8] = {v0.x, v0.y, v0.z, v0.w, v1.x, v1.y, v1.z, v1.w};
        float sx = 0.f;
        unsigned m0 = 0, m1 = 0;
        float x25[8];
        #pragma unroll
        for (int j = 0; j < 8; j++) {
            sx += x[j];
            x25[j] = x[j] + 0.25f;
            if (x[j]   < 0.f) m0 |= BITS[j];
            if (x25[j] < 0.f) m1 |= BITS[j];
        }
        #pragma unroll
        for (int jj = 0; jj < 4; jj++) {
            xp[tt][0][jj] = pk2(fabsf(x[2*jj]),   fabsf(x[2*jj+1]));
            xp[tt][1][jj] = pk2(fabsf(x25[2*jj]), fabsf(x25[2*jj+1]));
        }
        p1c[tt] = -0.5f * sx - 0.5f;
        maskx[tt][0] = m0;  px[tt][0] = (__popc(m0) & 1) << 31;
        maskx[tt][1] = m1;  px[tt][1] = (__popc(m1) & 1) << 31;
    }

    float best[2] = {-1e30f, -1e30f};
    int   bA[2]   = {0, 0};

    #pragma unroll
    for (int k = 0; k < 8; k++) {
        const int A = lane + (k << 5);
        const ulonglong2* pa = reinterpret_cast<const ulonglong2*>(s_a[A]);
        ulonglong2 q0 = pa[0], q1 = pa[1];         // (a0,a1),(a2,a3),(a4,a5),(a6,a7)
        const float nas  = s_norm[A];
        const int   ns   = __float_as_int(nas);    // sign bit = sign(a7)
        const float nabs = fabsf(nas);

        #pragma unroll
        for (int tt = 0; tt < 2; tt++) {
            SMM s0 = score8(xp[tt][0][0], xp[tt][0][1], xp[tt][0][2], xp[tt][0][3],
                            q0.x, q0.y, q1.x, q1.y);
            SMM s1 = score8(xp[tt][1][0], xp[tt][1][1], xp[tt][1][2], xp[tt][1][3],
                            q0.x, q0.y, q1.x, q1.y);
            // odd total parity (row-parity XOR sign(a7)) -> flip cheapest component
            float Sp0 = ((ns ^ px[tt][0]) < 0) ? fmaf(-2.f, s0.mn, s0.S) : s0.S;
            float Sp1 = ((ns ^ px[tt][1]) < 0) ? fmaf(-2.f, s1.mn, s1.S) : s1.S;
            float sc0 = fmaf(2.f, Sp0, -nabs);
            float sc1 = fmaf(2.f, Sp1, -nabs) + p1c[tt];
            float scm = fmaxf(sc0, sc1);           // parity re-decided at winner
            if (scm > best[tt]) { best[tt] = scm; bA[tt] = A; }   // first-wins: lowest A
        }
    }

    #pragma unroll
    for (int tt = 0; tt < 2; tt++) {
        // Warp argmax (butterfly; tie -> lowest A, matching argmax first-max).
        float b = best[tt]; int cA = bA[tt];
        #pragma unroll
        for (int off = 16; off; off >>= 1) {
            float ob = __shfl_xor_sync(0xffffffffu, b,  off);
            int   oc = __shfl_xor_sync(0xffffffffu, cA, off);
            if (ob > b || (ob == b && oc < cA)) { b = ob; cA = oc; }
        }

        // Winner recompute (all lanes, broadcast LDS) with the SAME packed ops.
        const ulonglong2* pa = reinterpret_cast<const ulonglong2*>(s_a[cA]);
        ulonglong2 q0 = pa[0], q1 = pa[1];
        const float nas  = s_norm[cA];
        const int   ns   = __float_as_int(nas);
        const float nabs = fabsf(nas);
        SMM s0 = score8(xp[tt][0][0], xp[tt][0][1], xp[tt][0][2], xp[tt][0][3],
                        q0.x, q0.y, q1.x, q1.y);
        SMM s1 = score8(xp[tt][1][0], xp[tt][1][1], xp[tt][1][2], xp[tt][1][3],
                        q0.x, q0.y, q1.x, q1.y);
        float Sp0 = ((ns ^ px[tt][0]) < 0) ? fmaf(-2.f, s0.mn, s0.S) : s0.S;
        float Sp1 = ((ns ^ px[tt][1]) < 0) ? fmaf(-2.f, s1.mn, s1.S) : s1.S;
        float sc0 = fmaf(2.f, Sp0, -nabs);
        float sc1 = fmaf(2.f, Sp1, -nabs) + p1c[tt];
        const int pw = (sc1 > sc0) ? 1 : 0;        // p0 wins exact ties

        // Scalar magnitudes of the winning parity for the first-min scan.
        unsigned long long y0 = pw ? xp[tt][1][0] : xp[tt][0][0];
        unsigned long long y1 = pw ? xp[tt][1][1] : xp[tt][0][1];
        unsigned long long y2 = pw ? xp[tt][1][2] : xp[tt][0][2];
        unsigned long long y3 = pw ? xp[tt][1][3] : xp[tt][0][3];
        float2 g0 = upk(mul2(y0, q0.x)), g1 = upk(mul2(y1, q0.y));
        float2 g2 = upk(mul2(y2, q1.x)), g3 = upk(mul2(y3, q1.y));
        float u[8] = {g0.x, g0.y, g1.x, g1.y, g2.x, g2.y, g3.x, g3.y};

        unsigned m = maskx[tt][pw] ^ ((ns < 0) ? 0x80u : 0u);
        float mnv = 1e30f; unsigned mnbit = 0;
        #pragma unroll
        for (int j = 0; j < 8; j++) {
            if (u[j] < mnv) { mnv = u[j]; mnbit = BITS[j]; }  // strict: first min
        }
        if (__popc(m) & 1) m ^= mnbit;
        const int bestc = (cA << 8) | ((int)m ^ pw);          // p=1 flips bit 0

        if (lane < 8) {
            out[(size_t)row[tt] * 8 + lane] = grid[(size_t)bestc * 8 + lane];  // vals
        }
        if (lane == 0) {
            out[65536 + row[tt]] = (float)bestc;              // idxs
            s_bestc[warp * 2 + tt] = bestc;                   // idx = (2c+dm)*2+tt
        }
    }
    __syncthreads();

    // ---- Block-local _pack_idxs (int32 / x64-disabled semantics: the reference's
    //      sign32 << 32 saturates to 0 in XLA; packed = int32 wrap of abs32).
    //      Word (i=ipair, j=8*half+cc): q[dm][tt] at s_bestc[(2*cc+dm)*2+tt].
    if (tid < 8) {
        const int cc = tid;                                   // 0..7
        const int j  = 8 * half + cc;
        int q00 = s_bestc[(2 * cc    ) * 2    ];              // (2i,   2j)
        int q10 = s_bestc[(2 * cc + 1) * 2    ];              // (2i+1, 2j)
        int q01 = s_bestc[(2 * cc    ) * 2 + 1];              // (2i,   2j+1)
        int q11 = s_bestc[(2 * cc + 1) * 2 + 1];              // (2i+1, 2j+1)

        unsigned abs32 = (unsigned)(q00 >> 8)
                       | ((unsigned)(q10 >> 8) << 8)
                       | ((unsigned)(q01 >> 8) << 16)
                       | ((unsigned)(q11 >> 8) << 24);

        // L from (i, j): L = (i>>3)<<7 | (j>>2)<<5 | (i&7)<<2 | (j&3)
        const int i = ipair;
        const int L = ((i >> 3) << 7) | ((j >> 2) << 5) | ((i & 7) << 2) | (j & 3);
        out[73728 + L] = (float)(int)abs32;                   // int32 wrap, f32 cast
    }
}

extern "C" void kernel_launch(void* const* d_in, const int* in_sizes, int n_in,
                              void* d_out, int out_size)
{
    const float* X         = (const float*)d_in[0];   // 256*32*8 = 65536
    const float* grid      = (const float*)d_in[1];   // 65536*8
    const float* grid_norm = (const float*)d_in[2];   // 65536
    float* out = (float*)d_out;                       // [vals | idxs | packed] fp32

    e8p_fused_kernel<<<256, 512>>>(X, grid, grid_norm, out);
}

// round 14
// speedup vs baseline: 1.1154x; 1.0625x over previous
#include <cuda_runtime.h>
#include <cstdint>

// ---- f32x2 packed helpers (sm_103a). Packed lanes round identically to scalar.
__device__ __forceinline__ unsigned long long mul2(unsigned long long a, unsigned long long b) {
    unsigned long long r;
    asm("mul.rn.f32x2 %0, %1, %2;" : "=l"(r) : "l"(a), "l"(b));
    return r;
}
__device__ __forceinline__ unsigned long long add2(unsigned long long a, unsigned long long b) {
    unsigned long long r;
    asm("add.rn.f32x2 %0, %1, %2;" : "=l"(r) : "l"(a), "l"(b));
    return r;
}
__device__ __forceinline__ unsigned long long pk2(float lo, float hi) {
    unsigned long long r;
    asm("mov.b64 %0, {%1, %2};" : "=l"(r) : "f"(lo), "f"(hi));
    return r;
}
__device__ __forceinline__ float2 upk(unsigned long long v) {
    float2 r;
    asm("mov.b64 {%0, %1}, %2;" : "=f"(r.x), "=f"(r.y) : "l"(v));
    return r;
}

struct SMM { float S, mn; };

// u_j = xp_j * a_j (all non-negative: xp = |x| pairs, a = |grid| pairs).
// S = balanced sum, mn = min. Fixed op shapes -> deterministic rounding.
__device__ __forceinline__ SMM score8(unsigned long long xp0, unsigned long long xp1,
                                      unsigned long long xp2, unsigned long long xp3,
                                      unsigned long long a01, unsigned long long a23,
                                      unsigned long long a45, unsigned long long a67)
{
    unsigned long long u0 = mul2(xp0, a01);
    unsigned long long u1 = mul2(xp1, a23);
    unsigned long long u2 = mul2(xp2, a45);
    unsigned long long u3 = mul2(xp3, a67);
    unsigned long long r  = add2(add2(u0, u1), add2(u2, u3));
    float2 rr = upk(r);
    float2 f0 = upk(u0), f1 = upk(u1), f2 = upk(u2), f3 = upk(u3);
    SMM o;
    o.S  = rr.x + rr.y;
    o.mn = fminf(fminf(fminf(f0.x, f0.y), fminf(f1.x, f1.y)),
                 fminf(fminf(f2.x, f2.y), fminf(f3.x, f3.y)));
    return o;
}

// Parity multiplier: -4.0f when (row parity XOR sign(a7)) is odd, else +0.0f.
// Pure fixed-latency ALU (no predicates): ((px^ns)>>31) & 0xC0800000.
__device__ __forceinline__ float par_m4(int px, int ns) {
    return __int_as_float(((px ^ ns) >> 31) & (int)0xC0800000);
}

// 128 blocks x 1024 threads. Block bk = ipair (row-pair of the 256x32 idx
// matrix); block covers ALL 32 columns (64 entries). Warp w (0..31): dm = w&1,
// c = w>>1 (0..15); entries (tt=0,1): m = 2*bk+dm, n = 2*c+tt.
// All 16 packed words of this row-pair live inside the block -> local pack.
// Table: s_a[A][0..7] = |grid[A<<8]| (only comp 7 can be negative);
// s_norm[A] = norm with sign(a7) folded in (stride-1 -> conflict-free LDS).
// NOTE: sign(a7) is NOT contiguous in A (R12 failure) -> general select always.
__global__ void __launch_bounds__(1024, 1) e8p_fused_kernel(
    const float* __restrict__ X,
    const float* __restrict__ grid,
    const float* __restrict__ grid_norm,
    float* __restrict__ out)
{
    __shared__ __align__(16) float s_a[256][12];   // stride 12 -> LDS.128 conflict-free
    __shared__ float s_norm[256];
    __shared__ int s_bestc[64];

    const int tid = threadIdx.x;
    if (tid < 256) {
        const int A = tid;
        const float4* g4 = reinterpret_cast<const float4*>(grid + ((size_t)A << 11));
        float4 a0 = g4[0], a1 = g4[1];
        const float na = grid_norm[A << 8];
        float4* d4 = reinterpret_cast<float4*>(s_a[A]);
        d4[0] = make_float4(fabsf(a0.x), fabsf(a0.y), fabsf(a0.z), fabsf(a0.w));
        d4[1] = make_float4(fabsf(a1.x), fabsf(a1.y), fabsf(a1.z), fabsf(a1.w));
        s_norm[A] = (a1.w < 0.f) ? -na : na;       // fold sign(a7) into norm
    }
    __syncthreads();

    const int warp = tid >> 5, lane = tid & 31;
    const int ipair = blockIdx.x;                  // 0..127
    const int dm = warp & 1, c = warp >> 1;        // c = 0..15

    // Component j of the value vector <- bit SHUF[j] of the sign field.
    // SHUF = {0,4,1,5,2,6,3,7} -> BITS[j] = 1 << SHUF[j].
    constexpr unsigned BITS[8] = {1u<<0, 1u<<4, 1u<<1, 1u<<5, 1u<<2, 1u<<6, 1u<<3, 1u<<7};

    int   row[2];
    float p1c[2];
    unsigned long long xp[2][2][4];                // [tt][parity][j-pair] packed |x|
    unsigned maskx[2][2];                          // [tt][parity] sign masks (BITS domain)
    int px[2][2];                                  // parity of maskx, in bit 31
    #pragma unroll
    for (int tt = 0; tt < 2; tt++) {
        row[tt] = (2 * ipair + dm) * 32 + 2 * c + tt;
        const float4* xr4 = reinterpret_cast<const float4*>(X + (size_t)row[tt] * 8);
        float4 v0 = xr4[0], v1 = xr4[1];
        float x[8] = {v0.x, v0.y, v0.z, v0.w, v1.x, v1.y, v1.z, v1.w};
        float sx = 0.f;
        unsigned m0 = 0, m1 = 0;
        float x25[8];
        #pragma unroll
        for (int j = 0; j < 8; j++) {
            sx += x[j];
            x25[j] = x[j] + 0.25f;
            if (x[j]   < 0.f) m0 |= BITS[j];
            if (x25[j] < 0.f) m1 |= BITS[j];
        }
        #pragma unroll
        for (int jj = 0; jj < 4; jj++) {
            xp[tt][0][jj] = pk2(fabsf(x[2*jj]),   fabsf(x[2*jj+1]));
            xp[tt][1][jj] = pk2(fabsf(x25[2*jj]), fabsf(x25[2*jj+1]));
        }
        p1c[tt] = -0.5f * sx - 0.5f;
        maskx[tt][0] = m0;  px[tt][0] = (__popc(m0) & 1) << 31;
        maskx[tt][1] = m1;  px[tt][1] = (__popc(m1) & 1) << 31;
    }

    float best[2] = {-1e30f, -1e30f};
    int   bA[2]   = {0, 0};

    #pragma unroll
    for (int k = 0; k < 8; k++) {
        const int A = lane + (k << 5);
        const ulonglong2* pa = reinterpret_cast<const ulonglong2*>(s_a[A]);
        ulonglong2 q0 = pa[0], q1 = pa[1];         // (a0,a1),(a2,a3),(a4,a5),(a6,a7)
        const float nas  = s_norm[A];
        const int   ns   = __float_as_int(nas);    // sign bit = sign(a7)
        const float nabs = fabsf(nas);

        #pragma unroll
        for (int tt = 0; tt < 2; tt++) {
            SMM s0 = score8(xp[tt][0][0], xp[tt][0][1], xp[tt][0][2], xp[tt][0][3],
                            q0.x, q0.y, q1.x, q1.y);
            SMM s1 = score8(xp[tt][1][0], xp[tt][1][1], xp[tt][1][2], xp[tt][1][3],
                            q0.x, q0.y, q1.x, q1.y);
            // odd total parity -> -4*mn correction, folded predicate-free.
            float sc0 = fmaf(2.f, s0.S, fmaf(par_m4(px[tt][0], ns), s0.mn, -nabs));
            float sc1 = fmaf(2.f, s1.S, fmaf(par_m4(px[tt][1], ns), s1.mn, -nabs)) + p1c[tt];
            float scm = fmaxf(sc0, sc1);           // parity re-decided at winner
            if (scm > best[tt]) { best[tt] = scm; bA[tt] = A; }   // first-wins: lowest A
        }
    }

    #pragma unroll
    for (int tt = 0; tt < 2; tt++) {
        // Warp argmax (butterfly; tie -> lowest A, matching argmax first-max).
        float b = best[tt]; int cA = bA[tt];
        #pragma unroll
        for (int off = 16; off; off >>= 1) {
            float ob = __shfl_xor_sync(0xffffffffu, b,  off);
            int   oc = __shfl_xor_sync(0xffffffffu, cA, off);
            if (ob > b || (ob == b && oc < cA)) { b = ob; cA = oc; }
        }

        // Winner recompute (all lanes, broadcast LDS) with the SAME formulas.
        const ulonglong2* pa = reinterpret_cast<const ulonglong2*>(s_a[cA]);
        ulonglong2 q0 = pa[0], q1 = pa[1];
        const float nas  = s_norm[cA];
        const int   ns   = __float_as_int(nas);
        const float nabs = fabsf(nas);
        SMM s0 = score8(xp[tt][0][0], xp[tt][0][1], xp[tt][0][2], xp[tt][0][3],
                        q0.x, q0.y, q1.x, q1.y);
        SMM s1 = score8(xp[tt][1][0], xp[tt][1][1], xp[tt][1][2], xp[tt][1][3],
                        q0.x, q0.y, q1.x, q1.y);
        float sc0 = fmaf(2.f, s0.S, fmaf(par_m4(px[tt][0], ns), s0.mn, -nabs));
        float sc1 = fmaf(2.f, s1.S, fmaf(par_m4(px[tt][1], ns), s1.mn, -nabs)) + p1c[tt];
        const int pw = (sc1 > sc0) ? 1 : 0;        // p0 wins exact ties

        // Scalar magnitudes of the winning parity for the first-min scan.
        unsigned long long y0 = pw ? xp[tt][1][0] : xp[tt][0][0];
        unsigned long long y1 = pw ? xp[tt][1][1] : xp[tt][0][1];
        unsigned long long y2 = pw ? xp[tt][1][2] : xp[tt][0][2];
        unsigned long long y3 = pw ? xp[tt][1][3] : xp[tt][0][3];
        float2 g0 = upk(mul2(y0, q0.x)), g1 = upk(mul2(y1, q0.y));
        float2 g2 = upk(mul2(y2, q1.x)), g3 = upk(mul2(y3, q1.y));
        float u[8] = {g0.x, g0.y, g1.x, g1.y, g2.x, g2.y, g3.x, g3.y};

        unsigned m = maskx[tt][pw] ^ ((ns < 0) ? 0x80u : 0u);
        float mnv = 1e30f; unsigned mnbit = 0;
        #pragma unroll
        for (int j = 0; j < 8; j++) {
            if (u[j] < mnv) { mnv = u[j]; mnbit = BITS[j]; }  // strict: first min
        }
        if (__popc(m) & 1) m ^= mnbit;
        const int bestc = (cA << 8) | ((int)m ^ pw);          // p=1 flips bit 0

        if (lane < 8) {
            out[(size_t)row[tt] * 8 + lane] = grid[(size_t)bestc * 8 + lane];  // vals
        }
        if (lane == 0) {
            out[65536 + row[tt]] = (float)bestc;              // idxs
            s_bestc[(2 * c + dm) * 2 + tt] = bestc;           // slot by (n-pair, dm, tt)
        }
    }
    __syncthreads();

    // ---- Block-local _pack_idxs (int32 / x64-disabled semantics: the reference's
    //      sign32 << 32 saturates to 0 in XLA; packed = int32 wrap of abs32).
    //      Word (i=ipair, j=0..15): q[dm][tt] at s_bestc[(2j+dm)*2+tt].
    if (tid < 16) {
        const int j = tid;                                    // 0..15
        int q00 = s_bestc[(2 * j    ) * 2    ];               // (2i,   2j)
        int q10 = s_bestc[(2 * j + 1) * 2    ];               // (2i+1, 2j)
        int q01 = s_bestc[(2 * j    ) * 2 + 1];               // (2i,   2j+1)
        int q11 = s_bestc[(2 * j + 1) * 2 + 1];               // (2i+1, 2j+1)

        unsigned abs32 = (unsigned)(q00 >> 8)
                       | ((unsigned)(q10 >> 8) << 8)
                       | ((unsigned)(q01 >> 8) << 16)
                       | ((unsigned)(q11 >> 8) << 24);

        // L from (i, j): L = (i>>3)<<7 | (j>>2)<<5 | (i&7)<<2 | (j&3)
        const int i = ipair;
        const int L = ((i >> 3) << 7) | ((j >> 2) << 5) | ((i & 7) << 2) | (j & 3);
        out[73728 + L] = (float)(int)abs32;                   // int32 wrap, f32 cast
    }
}

extern "C" void kernel_launch(void* const* d_in, const int* in_sizes, int n_in,
                              void* d_out, int out_size)
{
    const float* X         = (const float*)d_in[0];   // 256*32*8 = 65536
    const float* grid      = (const float*)d_in[1];   // 65536*8
    const float* grid_norm = (const float*)d_in[2];   // 65536
    float* out = (float*)d_out;                       // [vals | idxs | packed] fp32

    e8p_fused_kernel<<<128, 1024>>>(X, grid, grid_norm, out);
}

// round 15
// speedup vs baseline: 1.1629x; 1.0426x over previous
#include <cuda_runtime.h>
#include <cstdint>

// ---- f32x2 packed helpers (sm_103a). Packed lanes round identically to scalar.
__device__ __forceinline__ unsigned long long mul2(unsigned long long a, unsigned long long b) {
    unsigned long long r;
    asm("mul.rn.f32x2 %0, %1, %2;" : "=l"(r) : "l"(a), "l"(b));
    return r;
}
__device__ __forceinline__ unsigned long long add2(unsigned long long a, unsigned long long b) {
    unsigned long long r;
    asm("add.rn.f32x2 %0, %1, %2;" : "=l"(r) : "l"(a), "l"(b));
    return r;
}
__device__ __forceinline__ unsigned long long pk2(float lo, float hi) {
    unsigned long long r;
    asm("mov.b64 %0, {%1, %2};" : "=l"(r) : "f"(lo), "f"(hi));
    return r;
}
__device__ __forceinline__ float2 upk(unsigned long long v) {
    float2 r;
    asm("mov.b64 {%0, %1}, %2;" : "=f"(r.x), "=f"(r.y) : "l"(v));
    return r;
}

struct SMM { float S, mn; };

// u_j = xp_j * a_j (all non-negative: xp = |x| pairs, a = |grid| pairs).
// S = balanced sum, mn = min. Fixed op shapes -> deterministic rounding.
__device__ __forceinline__ SMM score8(unsigned long long xp0, unsigned long long xp1,
                                      unsigned long long xp2, unsigned long long xp3,
                                      unsigned long long a01, unsigned long long a23,
                                      unsigned long long a45, unsigned long long a67)
{
    unsigned long long u0 = mul2(xp0, a01);
    unsigned long long u1 = mul2(xp1, a23);
    unsigned long long u2 = mul2(xp2, a45);
    unsigned long long u3 = mul2(xp3, a67);
    unsigned long long r  = add2(add2(u0, u1), add2(u2, u3));
    float2 rr = upk(r);
    float2 f0 = upk(u0), f1 = upk(u1), f2 = upk(u2), f3 = upk(u3);
    SMM o;
    o.S  = rr.x + rr.y;
    o.mn = fminf(fminf(fminf(f0.x, f0.y), fminf(f1.x, f1.y)),
                 fminf(fminf(f2.x, f2.y), fminf(f3.x, f3.y)));
    return o;
}

// Parity multiplier: -4.0f when (row parity XOR sign(a7)) is odd, else +0.0f.
// Pure fixed-latency ALU (no predicates): ((px^ns)>>31) & 0xC0800000.
__device__ __forceinline__ float par_m4(int px, int ns) {
    return __int_as_float(((px ^ ns) >> 31) & (int)0xC0800000);
}

// 128 blocks x 1024 threads. Block bk = ipair (row-pair of the 256x32 idx
// matrix); block covers ALL 32 columns (64 entries). Warp w (0..31): dm = w&1,
// c = w>>1 (0..15); entries (tt=0,1): m = 2*bk+dm, n = 2*c+tt.
// All 16 packed words of this row-pair live inside the block -> local pack.
// Table: s_a[A][0..7] = |grid[A<<8]| (only comp 7 can be negative);
// s_norm[A] = norm with sign(a7) folded in (stride-1 -> conflict-free LDS).
// NOTE: sign(a7) is NOT contiguous in A (R12 failure) -> general select always.
// Best-tracking: per row TWO chains (even-k / odd-k); each scans its ascending
// A-subsequence with strict '>' (keeps lowest-A max); merge picks greater or
// equal-with-lower-A => identical to global ascending-A first-max.
__global__ void __launch_bounds__(1024, 1) e8p_fused_kernel(
    const float* __restrict__ X,
    const float* __restrict__ grid,
    const float* __restrict__ grid_norm,
    float* __restrict__ out)
{
    __shared__ __align__(16) float s_a[256][12];   // stride 12 -> LDS.128 conflict-free
    __shared__ float s_norm[256];
    __shared__ int s_bestc[64];

    const int tid = threadIdx.x;
    if (tid < 256) {
        const int A = tid;
        const float4* g4 = reinterpret_cast<const float4*>(grid + ((size_t)A << 11));
        float4 a0 = g4[0], a1 = g4[1];
        const float na = grid_norm[A << 8];
        float4* d4 = reinterpret_cast<float4*>(s_a[A]);
        d4[0] = make_float4(fabsf(a0.x), fabsf(a0.y), fabsf(a0.z), fabsf(a0.w));
        d4[1] = make_float4(fabsf(a1.x), fabsf(a1.y), fabsf(a1.z), fabsf(a1.w));
        s_norm[A] = (a1.w < 0.f) ? -na : na;       // fold sign(a7) into norm
    }
    __syncthreads();

    const int warp = tid >> 5, lane = tid & 31;
    const int ipair = blockIdx.x;                  // 0..127
    const int dm = warp & 1, c = warp >> 1;        // c = 0..15

    // Component j of the value vector <- bit SHUF[j] of the sign field.
    // SHUF = {0,4,1,5,2,6,3,7} -> BITS[j] = 1 << SHUF[j].
    constexpr unsigned BITS[8] = {1u<<0, 1u<<4, 1u<<1, 1u<<5, 1u<<2, 1u<<6, 1u<<3, 1u<<7};

    float p1c[2];
    unsigned long long xp[2][2][4];                // [tt][parity][j-pair] packed |x|
    unsigned maskpk = 0;                           // 4x 8-bit sign masks: bits[tt*16+par*8 ..]
    int px[2][2];                                  // parity of mask, in bit 31
    #pragma unroll
    for (int tt = 0; tt < 2; tt++) {
        const int row = (2 * ipair + dm) * 32 + 2 * c + tt;
        const float4* xr4 = reinterpret_cast<const float4*>(X + (size_t)row * 8);
        float4 v0 = xr4[0], v1 = xr4[1];
        float x[8] = {v0.x, v0.y, v0.z, v0.w, v1.x, v1.y, v1.z, v1.w};
        float sx = 0.f;
        unsigned m0 = 0, m1 = 0;
        float x25[8];
        #pragma unroll
        for (int j = 0; j < 8; j++) {
            sx += x[j];
            x25[j] = x[j] + 0.25f;
            if (x[j]   < 0.f) m0 |= BITS[j];
            if (x25[j] < 0.f) m1 |= BITS[j];
        }
        #pragma unroll
        for (int jj = 0; jj < 4; jj++) {
            xp[tt][0][jj] = pk2(fabsf(x[2*jj]),   fabsf(x[2*jj+1]));
            xp[tt][1][jj] = pk2(fabsf(x25[2*jj]), fabsf(x25[2*jj+1]));
        }
        p1c[tt] = -0.5f * sx - 0.5f;
        maskpk |= (m0 << (tt * 16)) | (m1 << (tt * 16 + 8));
        px[tt][0] = (__popc(m0) & 1) << 31;
        px[tt][1] = (__popc(m1) & 1) << 31;
    }

    // [tt][k&1] chains: even-k covers A = lane+{0,64,128,192}, odd-k the rest.
    float best[2][2] = {{-1e30f, -1e30f}, {-1e30f, -1e30f}};
    int   bA[2][2]   = {{0, 0}, {0, 0}};

    #pragma unroll
    for (int k = 0; k < 8; k++) {
        const int kb = k & 1;                      // compile-time under full unroll
        const int A = lane + (k << 5);
        const ulonglong2* pa = reinterpret_cast<const ulonglong2*>(s_a[A]);
        ulonglong2 q0 = pa[0], q1 = pa[1];         // (a0,a1),(a2,a3),(a4,a5),(a6,a7)
        const float nas  = s_norm[A];
        const int   ns   = __float_as_int(nas);    // sign bit = sign(a7)
        const float nabs = fabsf(nas);

        #pragma unroll
        for (int tt = 0; tt < 2; tt++) {
            SMM s0 = score8(xp[tt][0][0], xp[tt][0][1], xp[tt][0][2], xp[tt][0][3],
                            q0.x, q0.y, q1.x, q1.y);
            SMM s1 = score8(xp[tt][1][0], xp[tt][1][1], xp[tt][1][2], xp[tt][1][3],
                            q0.x, q0.y, q1.x, q1.y);
            // odd total parity -> -4*mn correction, folded predicate-free.
            float sc0 = fmaf(2.f, s0.S, fmaf(par_m4(px[tt][0], ns), s0.mn, -nabs));
            float sc1 = fmaf(2.f, s1.S, fmaf(par_m4(px[tt][1], ns), s1.mn, -nabs)) + p1c[tt];
            float scm = fmaxf(sc0, sc1);           // parity re-decided at winner
            if (scm > best[tt][kb]) { best[tt][kb] = scm; bA[tt][kb] = A; }  // first-wins
        }
    }

    #pragma unroll
    for (int tt = 0; tt < 2; tt++) {
        // Merge even/odd chains: greater wins; exact tie -> lower A (global first-max).
        float b; int cA;
        if (best[tt][1] > best[tt][0] ||
            (best[tt][1] == best[tt][0] && bA[tt][1] < bA[tt][0]))
             { b = best[tt][1]; cA = bA[tt][1]; }
        else { b = best[tt][0]; cA = bA[tt][0]; }

        // Warp argmax (butterfly; tie -> lowest A, matching argmax first-max).
        #pragma unroll
        for (int off = 16; off; off >>= 1) {
            float ob = __shfl_xor_sync(0xffffffffu, b,  off);
            int   oc = __shfl_xor_sync(0xffffffffu, cA, off);
            if (ob > b || (ob == b && oc < cA)) { b = ob; cA = oc; }
        }

        // Winner recompute (all lanes, broadcast LDS) with the SAME formulas.
        const ulonglong2* pa = reinterpret_cast<const ulonglong2*>(s_a[cA]);
        ulonglong2 q0 = pa[0], q1 = pa[1];
        const float nas  = s_norm[cA];
        const int   ns   = __float_as_int(nas);
        const float nabs = fabsf(nas);
        SMM s0 = score8(xp[tt][0][0], xp[tt][0][1], xp[tt][0][2], xp[tt][0][3],
                        q0.x, q0.y, q1.x, q1.y);
        SMM s1 = score8(xp[tt][1][0], xp[tt][1][1], xp[tt][1][2], xp[tt][1][3],
                        q0.x, q0.y, q1.x, q1.y);
        float sc0 = fmaf(2.f, s0.S, fmaf(par_m4(px[tt][0], ns), s0.mn, -nabs));
        float sc1 = fmaf(2.f, s1.S, fmaf(par_m4(px[tt][1], ns), s1.mn, -nabs)) + p1c[tt];
        const int pw = (sc1 > sc0) ? 1 : 0;        // p0 wins exact ties

        // Scalar magnitudes of the winning parity for the first-min scan.
        unsigned long long y0 = pw ? xp[tt][1][0] : xp[tt][0][0];
        unsigned long long y1 = pw ? xp[tt][1][1] : xp[tt][0][1];
        unsigned long long y2 = pw ? xp[tt][1][2] : xp[tt][0][2];
        unsigned long long y3 = pw ? xp[tt][1][3] : xp[tt][0][3];
        float2 g0 = upk(mul2(y0, q0.x)), g1 = upk(mul2(y1, q0.y));
        float2 g2 = upk(mul2(y2, q1.x)), g3 = upk(mul2(y3, q1.y));
        float u[8] = {g0.x, g0.y, g1.x, g1.y, g2.x, g2.y, g3.x, g3.y};

        unsigned m = ((maskpk >> (tt * 16 + pw * 8)) & 0xFFu) ^ ((ns < 0) ? 0x80u : 0u);
        float mnv = 1e30f; unsigned mnbit = 0;
        #pragma unroll
        for (int j = 0; j < 8; j++) {
            if (u[j] < mnv) { mnv = u[j]; mnbit = BITS[j]; }  // strict: first min
        }
        if (__popc(m) & 1) m ^= mnbit;
        const int bestc = (cA << 8) | ((int)m ^ pw);          // p=1 flips bit 0

        const int row = (2 * ipair + dm) * 32 + 2 * c + tt;
        if (lane < 8) {
            out[(size_t)row * 8 + lane] = grid[(size_t)bestc * 8 + lane];  // vals
        }
        if (lane == 0) {
            out[65536 + row] = (float)bestc;              // idxs
            s_bestc[(2 * c + dm) * 2 + tt] = bestc;       // slot by (n-pair, dm, tt)
        }
    }
    __syncthreads();

    // ---- Block-local _pack_idxs (int32 / x64-disabled semantics: the reference's
    //      sign32 << 32 saturates to 0 in XLA; packed = int32 wrap of abs32).
    //      Word (i=ipair, j=0..15): q[dm][tt] at s_bestc[(2j+dm)*2+tt].
    if (tid < 16) {
        const int j = tid;                                    // 0..15
        int q00 = s_bestc[(2 * j    ) * 2    ];               // (2i,   2j)
        int q10 = s_bestc[(2 * j + 1) * 2    ];               // (2i+1, 2j)
        int q01 = s_bestc[(2 * j    ) * 2 + 1];               // (2i,   2j+1)
        int q11 = s_bestc[(2 * j + 1) * 2 + 1];               // (2i+1, 2j+1)

        unsigned abs32 = (unsigned)(q00 >> 8)
                       | ((unsigned)(q10 >> 8) << 8)
                       | ((unsigned)(q01 >> 8) << 16)
                       | ((unsigned)(q11 >> 8) << 24);

        // L from (i, j): L = (i>>3)<<7 | (j>>2)<<5 | (i&7)<<2 | (j&3)
        const int i = ipair;
        const int L = ((i >> 3) << 7) | ((j >> 2) << 5) | ((i & 7) << 2) | (j & 3);
        out[73728 + L] = (float)(int)abs32;                   // int32 wrap, f32 cast
    }
}

extern "C" void kernel_launch(void* const* d_in, const int* in_sizes, int n_in,
                              void* d_out, int out_size)
{
    const float* X         = (const float*)d_in[0];   // 256*32*8 = 65536
    const float* grid      = (const float*)d_in[1];   // 65536*8
    const float* grid_norm = (const float*)d_in[2];   // 65536
    float* out = (float*)d_out;                       // [vals | idxs | packed] fp32

    e8p_fused_kernel<<<128, 1024>>>(X, grid, grid_norm, out);
}